// round 1
// baseline (speedup 1.0000x reference)
#include <cuda_runtime.h>

#define NN   50000
#define HIDD 64
#define EE   800000
#define EPN  100000
#define BNEPS 1e-5f

// ---- scratch (static device globals; no allocation) ----
__device__ float g_x[NN * HIDD];
__device__ float g_h[NN * HIDD];
__device__ float g_agg[NN * HIDD];
__device__ float g_dis[NN];
__device__ int   g_deg[NN];
__device__ int   g_start[NN + 1];
__device__ int   g_cursor[NN];
__device__ int2  g_csr[EE];          // {src_row, bitcast(norm)}
__device__ float g_stats[2 * HIDD];  // [sum(64), sumsq(64)]

// -------------------- degree / normalization --------------------

__global__ void zero_deg_k() {
    int i = blockIdx.x * blockDim.x + threadIdx.x;
    if (i < NN) g_deg[i] = 0;
}

__global__ void degree_k(const int* __restrict__ ei) {
    int e = blockIdx.x * blockDim.x + threadIdx.x;
    if (e < EE) atomicAdd(&g_deg[ei[EE + e]], 1);
}

__global__ void dis_k() {
    int i = blockIdx.x * blockDim.x + threadIdx.x;
    if (i < NN) g_dis[i] = rsqrtf((float)(g_deg[i] + 1));  // +1 self loop; always > 0
}

#define SCHUNK ((NN + 1023) / 1024)
__global__ __launch_bounds__(1024) void scan_k() {
    __shared__ int sm[1024];
    int t  = threadIdx.x;
    int lo = t * SCHUNK;
    int hi = min(lo + SCHUNK, NN);
    int s = 0;
    for (int i = lo; i < hi; i++) s += g_deg[i];
    sm[t] = s;
    __syncthreads();
    for (int off = 1; off < 1024; off <<= 1) {
        int v = (t >= off) ? sm[t - off] : 0;
        __syncthreads();
        sm[t] += v;
        __syncthreads();
    }
    int base = (t > 0) ? sm[t - 1] : 0;
    for (int i = lo; i < hi; i++) {
        g_start[i]  = base;
        g_cursor[i] = base;
        base += g_deg[i];
    }
    if (t == 0) g_start[NN] = sm[1023];
}

__global__ void csr_build_k(const int* __restrict__ ei) {
    int e = blockIdx.x * blockDim.x + threadIdx.x;
    if (e >= EE) return;
    int r = ei[e];
    int c = ei[EE + e];
    int p = atomicAdd(&g_cursor[c], 1);
    float w = g_dis[r] * g_dis[c];
    g_csr[p] = make_int2(r, __float_as_int(w));
}

// -------------------- GEMM: out[row,c] = (ACC? out:0) + sum_k A[row,k]*W[k,c] (+bias) ----

template <bool ACC, bool BIAS>
__global__ __launch_bounds__(256) void gemm64_k(const float* __restrict__ A,
                                                const float* __restrict__ W,
                                                const float* __restrict__ bias,
                                                float* __restrict__ out) {
    __shared__ float xs[32 * 64];
    int tid  = threadIdx.x;
    int c    = tid & 63;
    int rq   = tid >> 6;
    int row0 = blockIdx.x * 32;

#pragma unroll
    for (int i = 0; i < 8; i++) {
        int idx = tid + i * 256;
        int row = row0 + (idx >> 6);
        xs[idx] = (row < NN) ? A[row * 64 + (idx & 63)] : 0.0f;
    }

    float wc[64];
#pragma unroll
    for (int k = 0; k < 64; k++) wc[k] = W[k * 64 + c];

    __syncthreads();

    const float4* xs4 = (const float4*)xs;
    float b = BIAS ? bias[c] : 0.0f;

    for (int r0 = 0; r0 < 8; r0++) {
        int r   = rq * 8 + r0;
        int row = row0 + r;
        if (row >= NN) break;
        float a0 = 0.f, a1 = 0.f, a2 = 0.f, a3 = 0.f;
#pragma unroll
        for (int k4 = 0; k4 < 16; k4 += 4) {
            float4 v0 = xs4[r * 16 + k4 + 0];
            float4 v1 = xs4[r * 16 + k4 + 1];
            float4 v2 = xs4[r * 16 + k4 + 2];
            float4 v3 = xs4[r * 16 + k4 + 3];
            a0 = fmaf(v0.x, wc[(k4 + 0) * 4 + 0], a0);
            a0 = fmaf(v0.y, wc[(k4 + 0) * 4 + 1], a0);
            a0 = fmaf(v0.z, wc[(k4 + 0) * 4 + 2], a0);
            a0 = fmaf(v0.w, wc[(k4 + 0) * 4 + 3], a0);
            a1 = fmaf(v1.x, wc[(k4 + 1) * 4 + 0], a1);
            a1 = fmaf(v1.y, wc[(k4 + 1) * 4 + 1], a1);
            a1 = fmaf(v1.z, wc[(k4 + 1) * 4 + 2], a1);
            a1 = fmaf(v1.w, wc[(k4 + 1) * 4 + 3], a1);
            a2 = fmaf(v2.x, wc[(k4 + 2) * 4 + 0], a2);
            a2 = fmaf(v2.y, wc[(k4 + 2) * 4 + 1], a2);
            a2 = fmaf(v2.z, wc[(k4 + 2) * 4 + 2], a2);
            a2 = fmaf(v2.w, wc[(k4 + 2) * 4 + 3], a2);
            a3 = fmaf(v3.x, wc[(k4 + 3) * 4 + 0], a3);
            a3 = fmaf(v3.y, wc[(k4 + 3) * 4 + 1], a3);
            a3 = fmaf(v3.z, wc[(k4 + 3) * 4 + 2], a3);
            a3 = fmaf(v3.w, wc[(k4 + 3) * 4 + 3], a3);
        }
        float res = (a0 + a1) + (a2 + a3) + b;
        int   o   = row * 64 + c;
        if (ACC) res += out[o];
        out[o] = res;
    }
}

// -------------------- gather aggregation (no float atomics) --------------------
// agg[n] = conv_b + dis[n]^2 * h[n] + sum_{edges into n} norm_e * h[src_e]
__global__ __launch_bounds__(256) void aggregate_k(const float* __restrict__ convb) {
    if (blockIdx.x == 0 && threadIdx.x < 128) g_stats[threadIdx.x] = 0.0f;

    int n    = blockIdx.x * 16 + (threadIdx.x >> 4);
    int lane = threadIdx.x & 15;
    if (n >= NN) return;

    const float4* h4 = (const float4*)g_h;
    float4 cb = ((const float4*)convb)[lane];
    float  d  = g_dis[n];
    float  w0 = d * d;
    float4 hv = h4[n * 16 + lane];

    float4 acc;
    acc.x = cb.x + w0 * hv.x;
    acc.y = cb.y + w0 * hv.y;
    acc.z = cb.z + w0 * hv.z;
    acc.w = cb.w + w0 * hv.w;

    int j = g_start[n];
    int e = g_start[n + 1];
    for (; j + 1 < e; j += 2) {
        int2  ra = g_csr[j];
        int2  rb = g_csr[j + 1];
        float wa = __int_as_float(ra.y);
        float wb = __int_as_float(rb.y);
        float4 va = h4[ra.x * 16 + lane];
        float4 vb = h4[rb.x * 16 + lane];
        acc.x += wa * va.x; acc.y += wa * va.y; acc.z += wa * va.z; acc.w += wa * va.w;
        acc.x += wb * vb.x; acc.y += wb * vb.y; acc.z += wb * vb.z; acc.w += wb * vb.w;
    }
    if (j < e) {
        int2  ra = g_csr[j];
        float wa = __int_as_float(ra.y);
        float4 va = h4[ra.x * 16 + lane];
        acc.x += wa * va.x; acc.y += wa * va.y; acc.z += wa * va.z; acc.w += wa * va.w;
    }
    ((float4*)g_agg)[n * 16 + lane] = acc;
}

// -------------------- BatchNorm --------------------

__global__ __launch_bounds__(256) void bnstats_k() {
    int c = threadIdx.x & 63;
    int q = threadIdx.x >> 6;
    float s = 0.f, s2 = 0.f;
    for (int r = blockIdx.x * 4 + q; r < NN; r += gridDim.x * 4) {
        float v = g_agg[r * 64 + c];
        s += v;
        s2 += v * v;
    }
    __shared__ float sm[512];
    sm[threadIdx.x]       = s;
    sm[256 + threadIdx.x] = s2;
    __syncthreads();
    if (q == 0) {
        s  = sm[c] + sm[64 + c] + sm[128 + c] + sm[192 + c];
        s2 = sm[256 + c] + sm[256 + 64 + c] + sm[256 + 128 + c] + sm[256 + 192 + c];
        atomicAdd(&g_stats[c], s);
        atomicAdd(&g_stats[64 + c], s2);
    }
}

__global__ __launch_bounds__(256) void bnapply_k(const float* __restrict__ gamma,
                                                 const float* __restrict__ beta) {
    int idx = blockIdx.x * blockDim.x + threadIdx.x;
    if (idx >= NN * 16) return;
    int c0 = (idx & 15) * 4;
    const float inv = 1.0f / (float)NN;
    float4 a = ((const float4*)g_agg)[idx];
    float4 x = ((float4*)g_x)[idx];

    float mu, var, sc, v;
    mu = g_stats[c0 + 0] * inv; var = g_stats[64 + c0 + 0] * inv - mu * mu;
    sc = rsqrtf(var + BNEPS) * gamma[c0 + 0];
    v  = (a.x - mu) * sc + beta[c0 + 0]; x.x += fmaxf(v, 0.f);

    mu = g_stats[c0 + 1] * inv; var = g_stats[64 + c0 + 1] * inv - mu * mu;
    sc = rsqrtf(var + BNEPS) * gamma[c0 + 1];
    v  = (a.y - mu) * sc + beta[c0 + 1]; x.y += fmaxf(v, 0.f);

    mu = g_stats[c0 + 2] * inv; var = g_stats[64 + c0 + 2] * inv - mu * mu;
    sc = rsqrtf(var + BNEPS) * gamma[c0 + 2];
    v  = (a.z - mu) * sc + beta[c0 + 2]; x.z += fmaxf(v, 0.f);

    mu = g_stats[c0 + 3] * inv; var = g_stats[64 + c0 + 3] * inv - mu * mu;
    sc = rsqrtf(var + BNEPS) * gamma[c0 + 3];
    v  = (a.w - mu) * sc + beta[c0 + 3]; x.w += fmaxf(v, 0.f);

    ((float4*)g_x)[idx] = x;
}

// -------------------- decoder --------------------

__global__ __launch_bounds__(256) void decode_k(const int* __restrict__ pe,
                                                float* __restrict__ out) {
    int g    = blockIdx.x * 16 + (threadIdx.x >> 4);
    int lane = threadIdx.x & 15;
    if (g >= EPN) return;   // grid sized exactly; never taken (keeps shfl mask full)
    int a = pe[2 * g];
    int b = pe[2 * g + 1];
    const float4* z4 = (const float4*)g_x;
    float4 va = z4[a * 16 + lane];
    float4 vb = z4[b * 16 + lane];
    float d = va.x * vb.x + va.y * vb.y + va.z * vb.z + va.w * vb.w;
    d += __shfl_down_sync(0xffffffffu, d, 8, 16);
    d += __shfl_down_sync(0xffffffffu, d, 4, 16);
    d += __shfl_down_sync(0xffffffffu, d, 2, 16);
    d += __shfl_down_sync(0xffffffffu, d, 1, 16);
    if (lane == 0) out[g] = d;
}

// -------------------- launcher --------------------

extern "C" void kernel_launch(void* const* d_in, const int* in_sizes, int n_in,
                              void* d_out, int out_size) {
    const int*   edge_index = (const int*)d_in[0];
    const int*   pred_edge  = (const int*)d_in[1];
    const float* id_emb     = (const float*)d_in[2];
    const float* n2v_emb    = (const float*)d_in[3];
    const float* proj_w     = (const float*)d_in[4];
    const float* proj_b     = (const float*)d_in[5];
    const float* conv_w     = (const float*)d_in[6];
    const float* conv_b     = (const float*)d_in[7];
    const float* bn_gamma   = (const float*)d_in[8];
    const float* bn_beta    = (const float*)d_in[9];
    float*       out        = (float*)d_out;

    float *x_p, *h_p;
    cudaGetSymbolAddress((void**)&x_p, g_x);
    cudaGetSymbolAddress((void**)&h_p, g_h);

    const int GEMM_BLOCKS = (NN + 31) / 32;     // 1563
    const int EDGE_BLOCKS = (EE + 255) / 256;   // 3125
    const int NODE_BLOCKS = (NN + 255) / 256;   // 196
    const int AGG_BLOCKS  = (NN + 15) / 16;     // 3125
    const int APL_BLOCKS  = (NN * 16 + 255) / 256;
    const int DEC_BLOCKS  = (EPN + 15) / 16;    // 6250

    // graph structure (amortized over both layers)
    zero_deg_k<<<NODE_BLOCKS, 256>>>();
    degree_k<<<EDGE_BLOCKS, 256>>>(edge_index);
    dis_k<<<NODE_BLOCKS, 256>>>();
    scan_k<<<1, 1024>>>();
    csr_build_k<<<EDGE_BLOCKS, 256>>>(edge_index);

    // input projection: x = id@Wtop + n2v@Wbot + b
    gemm64_k<false, false><<<GEMM_BLOCKS, 256>>>(id_emb, proj_w, nullptr, x_p);
    gemm64_k<true, true><<<GEMM_BLOCKS, 256>>>(n2v_emb, proj_w + 64 * 64, proj_b, x_p);

    for (int l = 0; l < 2; l++) {
        gemm64_k<false, false><<<GEMM_BLOCKS, 256>>>(x_p, conv_w + l * 64 * 64, nullptr, h_p);
        aggregate_k<<<AGG_BLOCKS, 256>>>(conv_b + l * 64);
        bnstats_k<<<256, 256>>>();
        bnapply_k<<<APL_BLOCKS, 256>>>(bn_gamma + l * 64, bn_beta + l * 64);
    }

    decode_k<<<DEC_BLOCKS, 256>>>(pred_edge, out);
}

// round 2
// speedup vs baseline: 1.3962x; 1.3962x over previous
#include <cuda_runtime.h>

#define NN   50000
#define HIDD 64
#define EE   800000
#define EPN  100000
#define BNEPS 1e-5f
#define SB   ((NN + 255) / 256)   // 196 scan blocks

// ---- scratch (static device globals; no allocation) ----
__device__ float g_x[NN * HIDD];
__device__ float g_h[NN * HIDD];
__device__ float g_agg[NN * HIDD];
__device__ float g_dis[NN];
__device__ int   g_deg[NN];
__device__ int   g_start[NN + 1];
__device__ int   g_cursor[NN];
__device__ int   g_bsum[SB];
__device__ int2  g_csr[EE];          // {src_row, bitcast(norm)}
__device__ float g_stats[2 * HIDD];  // [sum(64), sumsq(64)]

// -------------------- degree --------------------

__global__ void zero_deg_k() {
    int i = blockIdx.x * blockDim.x + threadIdx.x;
    if (i < NN) g_deg[i] = 0;
}

__global__ void degree_k(const int* __restrict__ ei) {
    int e = blockIdx.x * blockDim.x + threadIdx.x;
    if (e < EE) atomicAdd(&g_deg[ei[EE + e]], 1);
}

// -------------------- 3-phase chip-wide exclusive scan of g_deg ------------
// phase 1: per-block sums (+ fused dis = rsqrt(deg+1))
__global__ __launch_bounds__(256) void scan1_k() {
    __shared__ int sm[256];
    int t = threadIdx.x;
    int i = blockIdx.x * 256 + t;
    int v = 0;
    if (i < NN) {
        v = g_deg[i];
        g_dis[i] = rsqrtf((float)(v + 1));   // +1 self loop; always > 0
    }
    sm[t] = v;
    __syncthreads();
#pragma unroll
    for (int off = 128; off > 0; off >>= 1) {
        if (t < off) sm[t] += sm[t + off];
        __syncthreads();
    }
    if (t == 0) g_bsum[blockIdx.x] = sm[0];
}

// phase 2: scan the 196 block sums (single tiny block)
__global__ __launch_bounds__(256) void scan2_k() {
    __shared__ int sm[256];
    int t = threadIdx.x;
    int v = (t < SB) ? g_bsum[t] : 0;
    sm[t] = v;
    __syncthreads();
#pragma unroll
    for (int off = 1; off < 256; off <<= 1) {
        int u = (t >= off) ? sm[t - off] : 0;
        __syncthreads();
        sm[t] += u;
        __syncthreads();
    }
    if (t < SB) g_bsum[t] = sm[t] - v;          // exclusive base per block
    if (t == SB - 1) g_start[NN] = sm[t];       // total
}

// phase 3: per-block exclusive scan + base
__global__ __launch_bounds__(256) void scan3_k() {
    __shared__ int sm[256];
    int t = threadIdx.x;
    int i = blockIdx.x * 256 + t;
    int v = (i < NN) ? g_deg[i] : 0;
    sm[t] = v;
    __syncthreads();
#pragma unroll
    for (int off = 1; off < 256; off <<= 1) {
        int u = (t >= off) ? sm[t - off] : 0;
        __syncthreads();
        sm[t] += u;
        __syncthreads();
    }
    if (i < NN) {
        int pos = g_bsum[blockIdx.x] + sm[t] - v;
        g_start[i]  = pos;
        g_cursor[i] = pos;
    }
}

__global__ void csr_build_k(const int* __restrict__ ei) {
    int e = blockIdx.x * blockDim.x + threadIdx.x;
    if (e >= EE) return;
    int r = ei[e];
    int c = ei[EE + e];
    int p = atomicAdd(&g_cursor[c], 1);
    float w = g_dis[r] * g_dis[c];
    g_csr[p] = make_int2(r, __float_as_int(w));
}

// -------------------- GEMM: out[row,c] = (ACC? out:0) + sum_k A[row,k]*W[k,c] (+bias) ----

template <bool ACC, bool BIAS>
__global__ __launch_bounds__(256) void gemm64_k(const float* __restrict__ A,
                                                const float* __restrict__ W,
                                                const float* __restrict__ bias,
                                                float* __restrict__ out) {
    __shared__ float xs[32 * 64];
    int tid  = threadIdx.x;
    int c    = tid & 63;
    int rq   = tid >> 6;
    int row0 = blockIdx.x * 32;

#pragma unroll
    for (int i = 0; i < 8; i++) {
        int idx = tid + i * 256;
        int row = row0 + (idx >> 6);
        xs[idx] = (row < NN) ? A[row * 64 + (idx & 63)] : 0.0f;
    }

    float wc[64];
#pragma unroll
    for (int k = 0; k < 64; k++) wc[k] = W[k * 64 + c];

    __syncthreads();

    const float4* xs4 = (const float4*)xs;
    float b = BIAS ? bias[c] : 0.0f;

    for (int r0 = 0; r0 < 8; r0++) {
        int r   = rq * 8 + r0;
        int row = row0 + r;
        if (row >= NN) break;
        float a0 = 0.f, a1 = 0.f, a2 = 0.f, a3 = 0.f;
#pragma unroll
        for (int k4 = 0; k4 < 16; k4 += 4) {
            float4 v0 = xs4[r * 16 + k4 + 0];
            float4 v1 = xs4[r * 16 + k4 + 1];
            float4 v2 = xs4[r * 16 + k4 + 2];
            float4 v3 = xs4[r * 16 + k4 + 3];
            a0 = fmaf(v0.x, wc[(k4 + 0) * 4 + 0], a0);
            a0 = fmaf(v0.y, wc[(k4 + 0) * 4 + 1], a0);
            a0 = fmaf(v0.z, wc[(k4 + 0) * 4 + 2], a0);
            a0 = fmaf(v0.w, wc[(k4 + 0) * 4 + 3], a0);
            a1 = fmaf(v1.x, wc[(k4 + 1) * 4 + 0], a1);
            a1 = fmaf(v1.y, wc[(k4 + 1) * 4 + 1], a1);
            a1 = fmaf(v1.z, wc[(k4 + 1) * 4 + 2], a1);
            a1 = fmaf(v1.w, wc[(k4 + 1) * 4 + 3], a1);
            a2 = fmaf(v2.x, wc[(k4 + 2) * 4 + 0], a2);
            a2 = fmaf(v2.y, wc[(k4 + 2) * 4 + 1], a2);
            a2 = fmaf(v2.z, wc[(k4 + 2) * 4 + 2], a2);
            a2 = fmaf(v2.w, wc[(k4 + 2) * 4 + 3], a2);
            a3 = fmaf(v3.x, wc[(k4 + 3) * 4 + 0], a3);
            a3 = fmaf(v3.y, wc[(k4 + 3) * 4 + 1], a3);
            a3 = fmaf(v3.z, wc[(k4 + 3) * 4 + 2], a3);
            a3 = fmaf(v3.w, wc[(k4 + 3) * 4 + 3], a3);
        }
        float res = (a0 + a1) + (a2 + a3) + b;
        int   o   = row * 64 + c;
        if (ACC) res += out[o];
        out[o] = res;
    }
}

// -------------------- gather aggregation (no float atomics) --------------------
// agg[n] = conv_b + dis[n]^2 * h[n] + sum_{edges into n} norm_e * h[src_e]
__global__ __launch_bounds__(256) void aggregate_k(const float* __restrict__ convb) {
    if (blockIdx.x == 0 && threadIdx.x < 128) g_stats[threadIdx.x] = 0.0f;

    int n    = blockIdx.x * 16 + (threadIdx.x >> 4);
    int lane = threadIdx.x & 15;
    if (n >= NN) return;

    const float4* h4 = (const float4*)g_h;
    float4 cb = ((const float4*)convb)[lane];
    float  d  = g_dis[n];
    float  w0 = d * d;
    float4 hv = h4[n * 16 + lane];

    float4 acc;
    acc.x = cb.x + w0 * hv.x;
    acc.y = cb.y + w0 * hv.y;
    acc.z = cb.z + w0 * hv.z;
    acc.w = cb.w + w0 * hv.w;

    int j = g_start[n];
    int e = g_start[n + 1];
    // 4x unrolled: keep 4 independent h-row loads in flight
    for (; j + 3 < e; j += 4) {
        int2  ra = g_csr[j + 0];
        int2  rb = g_csr[j + 1];
        int2  rc = g_csr[j + 2];
        int2  rd = g_csr[j + 3];
        float4 va = h4[ra.x * 16 + lane];
        float4 vb = h4[rb.x * 16 + lane];
        float4 vc = h4[rc.x * 16 + lane];
        float4 vd = h4[rd.x * 16 + lane];
        float wa = __int_as_float(ra.y);
        float wb = __int_as_float(rb.y);
        float wc = __int_as_float(rc.y);
        float wd = __int_as_float(rd.y);
        acc.x += wa * va.x; acc.y += wa * va.y; acc.z += wa * va.z; acc.w += wa * va.w;
        acc.x += wb * vb.x; acc.y += wb * vb.y; acc.z += wb * vb.z; acc.w += wb * vb.w;
        acc.x += wc * vc.x; acc.y += wc * vc.y; acc.z += wc * vc.z; acc.w += wc * vc.w;
        acc.x += wd * vd.x; acc.y += wd * vd.y; acc.z += wd * vd.z; acc.w += wd * vd.w;
    }
    for (; j < e; j++) {
        int2  ra = g_csr[j];
        float wa = __int_as_float(ra.y);
        float4 va = h4[ra.x * 16 + lane];
        acc.x += wa * va.x; acc.y += wa * va.y; acc.z += wa * va.z; acc.w += wa * va.w;
    }
    ((float4*)g_agg)[n * 16 + lane] = acc;
}

// -------------------- BatchNorm --------------------

__global__ __launch_bounds__(256) void bnstats_k() {
    int c = threadIdx.x & 63;
    int q = threadIdx.x >> 6;
    float s = 0.f, s2 = 0.f;
    for (int r = blockIdx.x * 4 + q; r < NN; r += gridDim.x * 4) {
        float v = g_agg[r * 64 + c];
        s += v;
        s2 += v * v;
    }
    __shared__ float sm[512];
    sm[threadIdx.x]       = s;
    sm[256 + threadIdx.x] = s2;
    __syncthreads();
    if (q == 0) {
        s  = sm[c] + sm[64 + c] + sm[128 + c] + sm[192 + c];
        s2 = sm[256 + c] + sm[256 + 64 + c] + sm[256 + 128 + c] + sm[256 + 192 + c];
        atomicAdd(&g_stats[c], s);
        atomicAdd(&g_stats[64 + c], s2);
    }
}

__global__ __launch_bounds__(256) void bnapply_k(const float* __restrict__ gamma,
                                                 const float* __restrict__ beta) {
    int idx = blockIdx.x * blockDim.x + threadIdx.x;
    if (idx >= NN * 16) return;
    int c0 = (idx & 15) * 4;
    const float inv = 1.0f / (float)NN;
    float4 a = ((const float4*)g_agg)[idx];
    float4 x = ((float4*)g_x)[idx];

    float mu, var, sc, v;
    mu = g_stats[c0 + 0] * inv; var = g_stats[64 + c0 + 0] * inv - mu * mu;
    sc = rsqrtf(var + BNEPS) * gamma[c0 + 0];
    v  = (a.x - mu) * sc + beta[c0 + 0]; x.x += fmaxf(v, 0.f);

    mu = g_stats[c0 + 1] * inv; var = g_stats[64 + c0 + 1] * inv - mu * mu;
    sc = rsqrtf(var + BNEPS) * gamma[c0 + 1];
    v  = (a.y - mu) * sc + beta[c0 + 1]; x.y += fmaxf(v, 0.f);

    mu = g_stats[c0 + 2] * inv; var = g_stats[64 + c0 + 2] * inv - mu * mu;
    sc = rsqrtf(var + BNEPS) * gamma[c0 + 2];
    v  = (a.z - mu) * sc + beta[c0 + 2]; x.z += fmaxf(v, 0.f);

    mu = g_stats[c0 + 3] * inv; var = g_stats[64 + c0 + 3] * inv - mu * mu;
    sc = rsqrtf(var + BNEPS) * gamma[c0 + 3];
    v  = (a.w - mu) * sc + beta[c0 + 3]; x.w += fmaxf(v, 0.f);

    ((float4*)g_x)[idx] = x;
}

// -------------------- decoder --------------------

__global__ __launch_bounds__(256) void decode_k(const int* __restrict__ pe,
                                                float* __restrict__ out) {
    int g    = blockIdx.x * 16 + (threadIdx.x >> 4);
    int lane = threadIdx.x & 15;
    if (g >= EPN) return;   // grid sized exactly; never taken (keeps shfl mask full)
    int a = pe[2 * g];
    int b = pe[2 * g + 1];
    const float4* z4 = (const float4*)g_x;
    float4 va = z4[a * 16 + lane];
    float4 vb = z4[b * 16 + lane];
    float d = va.x * vb.x + va.y * vb.y + va.z * vb.z + va.w * vb.w;
    d += __shfl_down_sync(0xffffffffu, d, 8, 16);
    d += __shfl_down_sync(0xffffffffu, d, 4, 16);
    d += __shfl_down_sync(0xffffffffu, d, 2, 16);
    d += __shfl_down_sync(0xffffffffu, d, 1, 16);
    if (lane == 0) out[g] = d;
}

// -------------------- launcher --------------------

extern "C" void kernel_launch(void* const* d_in, const int* in_sizes, int n_in,
                              void* d_out, int out_size) {
    const int*   edge_index = (const int*)d_in[0];
    const int*   pred_edge  = (const int*)d_in[1];
    const float* id_emb     = (const float*)d_in[2];
    const float* n2v_emb    = (const float*)d_in[3];
    const float* proj_w     = (const float*)d_in[4];
    const float* proj_b     = (const float*)d_in[5];
    const float* conv_w     = (const float*)d_in[6];
    const float* conv_b     = (const float*)d_in[7];
    const float* bn_gamma   = (const float*)d_in[8];
    const float* bn_beta    = (const float*)d_in[9];
    float*       out        = (float*)d_out;

    float *x_p, *h_p;
    cudaGetSymbolAddress((void**)&x_p, g_x);
    cudaGetSymbolAddress((void**)&h_p, g_h);

    const int GEMM_BLOCKS = (NN + 31) / 32;     // 1563
    const int EDGE_BLOCKS = (EE + 255) / 256;   // 3125
    const int NODE_BLOCKS = (NN + 255) / 256;   // 196
    const int AGG_BLOCKS  = (NN + 15) / 16;     // 3125
    const int APL_BLOCKS  = (NN * 16 + 255) / 256;
    const int DEC_BLOCKS  = (EPN + 15) / 16;    // 6250

    // graph structure (amortized over both layers)
    zero_deg_k<<<NODE_BLOCKS, 256>>>();
    degree_k<<<EDGE_BLOCKS, 256>>>(edge_index);
    scan1_k<<<SB, 256>>>();
    scan2_k<<<1, 256>>>();
    scan3_k<<<SB, 256>>>();
    csr_build_k<<<EDGE_BLOCKS, 256>>>(edge_index);

    // input projection: x = id@Wtop + n2v@Wbot + b
    gemm64_k<false, false><<<GEMM_BLOCKS, 256>>>(id_emb, proj_w, nullptr, x_p);
    gemm64_k<true, true><<<GEMM_BLOCKS, 256>>>(n2v_emb, proj_w + 64 * 64, proj_b, x_p);

    for (int l = 0; l < 2; l++) {
        gemm64_k<false, false><<<GEMM_BLOCKS, 256>>>(x_p, conv_w + l * 64 * 64, nullptr, h_p);
        aggregate_k<<<AGG_BLOCKS, 256>>>(conv_b + l * 64);
        bnstats_k<<<256, 256>>>();
        bnapply_k<<<APL_BLOCKS, 256>>>(bn_gamma + l * 64, bn_beta + l * 64);
    }

    decode_k<<<DEC_BLOCKS, 256>>>(pred_edge, out);
}